// round 6
// baseline (speedup 1.0000x reference)
#include <cuda_runtime.h>
#include <math.h>

// Problem dims
#define BSZ   64
#define NMEM  512
#define WD    64
#define RH    4
#define OUTD  256
#define IND   256
#define IFC   471     // interface size
#define CD    727     // controller dim
#define G3    2181    // 3*CD

// Output layout offsets (concatenated flattened tuple, f32)
#define OFF_Y      0
#define OFF_MN     16384
#define OFF_USAGE  2113536
#define OFF_LN     2146304
#define OFF_WP     18923520
#define OFF_WR     18956288
#define OFF_WW     19087360
#define OFF_HC     19120128

// Scratch (no cudaMalloc allowed)
__device__ float g_mx[128 * G3];
__device__ float g_mh[128 * G3];
__device__ float g_iface[128 * IFC];
__device__ __align__(16) float g_fwdpart[BSZ * 8 * NMEM * RH];
__device__ __align__(16) float g_bwdpart[BSZ * 8 * NMEM * RH];

__device__ __forceinline__ float sigmoidf_(float x) { return 1.f / (1.f + expf(-x)); }
__device__ __forceinline__ float softplusf_(float x) { return fmaxf(x, 0.f) + log1pf(expf(-fabsf(x))); }

// Block-wide reductions for 512 threads: shuffle within warp + 16-slot shared.
__device__ __forceinline__ float blk_red_max(float v, float* sb, int t) {
#pragma unroll
    for (int o = 16; o; o >>= 1) v = fmaxf(v, __shfl_xor_sync(0xffffffffu, v, o));
    __syncthreads();
    if ((t & 31) == 0) sb[t >> 5] = v;
    __syncthreads();
    float r = sb[0];
#pragma unroll
    for (int i = 1; i < 16; i++) r = fmaxf(r, sb[i]);
    return r;
}
__device__ __forceinline__ float blk_red_sum(float v, float* sb, int t) {
#pragma unroll
    for (int o = 16; o; o >>= 1) v += __shfl_xor_sync(0xffffffffu, v, o);
    __syncthreads();
    if ((t & 31) == 0) sb[t >> 5] = v;
    __syncthreads();
    float r = 0.f;
#pragma unroll
    for (int i = 0; i < 16; i++) r += sb[i];
    return r;
}

// ---------------------------------------------------------------------------
// 64x64-tile GEMM: C[M,N] = A[M,K] @ B[K,N] (+bias). 256 threads, 4x4 micro,
// K-tile 16. Scalar global loads (odd strides). M=128 (grid.y=2 exact).
// ---------------------------------------------------------------------------
__device__ __forceinline__ void gemm64_body(const float* __restrict__ A,
                                            const float* __restrict__ B,
                                            const float* __restrict__ bias,
                                            float* __restrict__ C,
                                            int N, int K) {
    __shared__ __align__(16) float Ast[16][68];  // [k][m] transposed, 16B-aligned rows
    __shared__ __align__(16) float Bs[16][64];
    int t = threadIdx.x;            // 256 threads
    int m0 = blockIdx.y * 64;
    int n0 = blockIdx.x * 64;
    if (n0 >= N) return;
    int tx = t & 15;                // 16 col groups x4
    int ty = t >> 4;                // 16 row groups x4
    float acc[4][4] = {};

    int am = t >> 2;                 // A-load: row within tile
    int ak = (t & 3) * 4;            // 4 consecutive k's
    int bc = t & 63;                 // B-load: col within tile
    int bk0 = t >> 6;                // 4 k's, stride 4

    for (int k0 = 0; k0 < K; k0 += 16) {
#pragma unroll
        for (int i = 0; i < 4; i++) {
            int k = ak + i;
            Ast[k][am] = (k0 + k < K) ? A[(m0 + am) * K + k0 + k] : 0.f;
        }
#pragma unroll
        for (int i = 0; i < 4; i++) {
            int k = bk0 + i * 4;
            Bs[k][bc] = ((k0 + k < K) && (n0 + bc < N)) ? B[(k0 + k) * N + n0 + bc] : 0.f;
        }
        __syncthreads();
#pragma unroll
        for (int kk = 0; kk < 16; kk++) {
            float4 a4 = *(const float4*)&Ast[kk][ty * 4];
            float4 b4 = *(const float4*)&Bs[kk][tx * 4];
            acc[0][0] += a4.x * b4.x; acc[0][1] += a4.x * b4.y;
            acc[0][2] += a4.x * b4.z; acc[0][3] += a4.x * b4.w;
            acc[1][0] += a4.y * b4.x; acc[1][1] += a4.y * b4.y;
            acc[1][2] += a4.y * b4.z; acc[1][3] += a4.y * b4.w;
            acc[2][0] += a4.z * b4.x; acc[2][1] += a4.z * b4.y;
            acc[2][2] += a4.z * b4.z; acc[2][3] += a4.z * b4.w;
            acc[3][0] += a4.w * b4.x; acc[3][1] += a4.w * b4.y;
            acc[3][2] += a4.w * b4.z; acc[3][3] += a4.w * b4.w;
        }
        __syncthreads();
    }
#pragma unroll
    for (int i = 0; i < 4; i++) {
        int row = m0 + ty * 4 + i;
#pragma unroll
        for (int j = 0; j < 4; j++) {
            int col = n0 + tx * 4 + j;
            if (col < N) {
                float v = acc[i][j];
                if (bias) v += bias[col];
                C[row * N + col] = v;
            }
        }
    }
}

// Dual launch: z=0 -> mx = X @ gru_k + b0 ; z=1 -> mh = H @ gru_rk + b1
__global__ void gemm_gru(const float* __restrict__ X, const float* __restrict__ H,
                         const float* __restrict__ gk, const float* __restrict__ grk,
                         const float* __restrict__ gb) {
    if (blockIdx.z == 0) gemm64_body(X, gk, gb, g_mx, G3, IND);
    else                 gemm64_body(H, grk, gb + G3, g_mh, G3, CD);
}

// ---------------------------------------------------------------------------
// 32x32-tile GEMM for the smaller iface matmul (more blocks -> occupancy)
// ---------------------------------------------------------------------------
__global__ void gemm_iface(const float* __restrict__ A, const float* __restrict__ B) {
    __shared__ __align__(16) float Ast[32][34];
    __shared__ __align__(16) float Bs[32][32];
    const int N = IFC, K = CD;
    int t = threadIdx.x;            // 128 threads
    int m0 = blockIdx.y * 32;
    int n0 = blockIdx.x * 32;
    int tx = t & 7;
    int ty = t >> 3;
    float acc[2][4] = {{0.f,0.f,0.f,0.f},{0.f,0.f,0.f,0.f}};

    for (int k0 = 0; k0 < K; k0 += 32) {
#pragma unroll
        for (int i = 0; i < 8; i++) {
            int e = t + i * 128;
            int k = e & 31, m = e >> 5;
            float v = 0.f;
            if (k0 + k < K) v = A[(m0 + m) * K + k0 + k];
            Ast[k][m] = v;
        }
#pragma unroll
        for (int i = 0; i < 8; i++) {
            int e = t + i * 128;
            int c = e & 31, k = e >> 5;
            float v = 0.f;
            if (k0 + k < K && n0 + c < N) v = B[(k0 + k) * N + n0 + c];
            Bs[k][c] = v;
        }
        __syncthreads();
#pragma unroll
        for (int kk = 0; kk < 32; kk++) {
            float2 a2 = *(const float2*)&Ast[kk][ty * 2];
            float4 b4 = *(const float4*)&Bs[kk][tx * 4];
            acc[0][0] += a2.x * b4.x; acc[0][1] += a2.x * b4.y;
            acc[0][2] += a2.x * b4.z; acc[0][3] += a2.x * b4.w;
            acc[1][0] += a2.y * b4.x; acc[1][1] += a2.y * b4.y;
            acc[1][2] += a2.y * b4.z; acc[1][3] += a2.y * b4.w;
        }
        __syncthreads();
    }
#pragma unroll
    for (int i = 0; i < 2; i++) {
        int row = m0 + ty * 2 + i;
#pragma unroll
        for (int j = 0; j < 4; j++) {
            int col = n0 + tx * 4 + j;
            if (col < N) g_iface[row * N + col] = acc[i][j];
        }
    }
}

// ---------------------------------------------------------------------------
// GRU combine: c = z*h + (1-z)*gelu(xh + r*rh)
// ---------------------------------------------------------------------------
__global__ void gru_combine(const float* __restrict__ h, float* __restrict__ hc_out) {
    int idx = blockIdx.x * blockDim.x + threadIdx.x;
    if (idx >= 128 * CD) return;
    int row = idx / CD, j = idx % CD;
    const float* mx = g_mx + row * G3;
    const float* mh = g_mh + row * G3;
    float z = sigmoidf_(mx[j] + mh[j]);
    float r = sigmoidf_(mx[CD + j] + mh[CD + j]);
    float hin = mx[2 * CD + j] + r * mh[2 * CD + j];
    float hh = hin * normcdff(hin);   // exact gelu
    float hv = h[idx];
    hc_out[idx] = z * hv + (1.f - z) * hh;
}

// ---------------------------------------------------------------------------
// Fused per-batch memory update (sort-free, tie-break-free two-range loop)
// 64 blocks x 512 threads
// ---------------------------------------------------------------------------
__global__ void memupdate_kernel(const float* __restrict__ W_read,
                                 const float* __restrict__ W_write,
                                 const float* __restrict__ usage,
                                 const float* __restrict__ M,
                                 const float* __restrict__ Wp,
                                 float* __restrict__ usage_out,
                                 float* __restrict__ Ww_out,
                                 float* __restrict__ Wp_out,
                                 float* __restrict__ Mn_out) {
    __shared__ float us[NMEM];
    __shared__ float wws[NMEM];
    __shared__ __align__(16) float nk[WD];
    __shared__ __align__(16) float es[WD];
    __shared__ __align__(16) float vs[WD];
    __shared__ float keyn[WD];
    __shared__ float sc[4];
    __shared__ float sb[16];
    int b = blockIdx.x, t = threadIdx.x;
    const float* ifw = g_iface + (2 * b + 1) * IFC;

    // --- usage_n ---
    float4 wr4 = *(const float4*)(W_read + (b * NMEM + t) * RH);
    float ret = (1.f - sigmoidf_(ifw[453]) * wr4.x)
              * (1.f - sigmoidf_(ifw[454]) * wr4.y)
              * (1.f - sigmoidf_(ifw[455]) * wr4.z)
              * (1.f - sigmoidf_(ifw[456]) * wr4.w);
    float u = usage[b * NMEM + t], w = W_write[b * NMEM + t];
    float un = (u + w - u * w) * ret;
    usage_out[b * NMEM + t] = un;
    us[t] = un;
    if (t < WD) {
        es[t] = sigmoidf_(ifw[325 + t]);
        vs[t] = ifw[389 + t];
        float kv = ifw[260 + t];
        keyn[t] = kv * kv;
    }
    __syncthreads();
    if (t == 0) {
        float s = 0.f;
        for (int i = 0; i < WD; i++) s += keyn[i];
        sc[0] = 1.f / sqrtf(fmaxf(s, 1e-12f));
        sc[1] = 1.f + softplusf_(ifw[324]);   // b_write
        sc[2] = sigmoidf_(ifw[457]);          // alloc_g
        sc[3] = sigmoidf_(ifw[458]);          // write_g
    }

    // --- W_alloc[n] = (1-u[n]) * prod_{key(m)<key(n)} u[m] ---
    // key order: (usage asc, index asc). Split at m=t to kill tie-break logic:
    //   m<t: tie -> smaller key -> include  => (um <= un)
    //   m>t: include only strictly smaller  => (um < un)
    float p = 1.f;
#pragma unroll 8
    for (int m = 0; m < t; m++) {
        float um = us[m];
        p *= (um <= un) ? um : 1.f;
    }
#pragma unroll 8
    for (int m = t + 1; m < NMEM; m++) {
        float um = us[m];
        p *= (um < un) ? um : 1.f;
    }
    float walloc = (1.f - un) * p;
    __syncthreads();
    if (t < WD) nk[t] = ifw[260 + t] * sc[0];
    __syncthreads();

    // --- write content lookup (float4) ---
    const float4* m4p = (const float4*)(M + (b * NMEM + t) * WD);
    const float4* nk4 = (const float4*)nk;
    float dot = 0.f, nrm = 0.f;
#pragma unroll
    for (int i = 0; i < 16; i++) {
        float4 m4 = m4p[i];
        float4 k4 = nk4[i];
        dot += m4.x * k4.x + m4.y * k4.y + m4.z * k4.z + m4.w * k4.w;
        nrm += m4.x * m4.x + m4.y * m4.y + m4.z * m4.z + m4.w * m4.w;
    }
    float s = dot * (1.f / sqrtf(fmaxf(nrm, 1e-12f))) * sc[1];
    float mxv = blk_red_max(s, sb, t);
    float e = expf(s - mxv);
    float ssum = blk_red_sum(e, sb, t);
    float wl = e / ssum;

    float ww = sc[3] * (sc[2] * walloc + (1.f - sc[2]) * wl);
    Ww_out[b * NMEM + t] = ww;
    wws[t] = ww;
    float wsum = blk_red_sum(ww, sb, t);   // barriers inside make wws visible
    // --- precedence ---
    Wp_out[b * NMEM + t] = (1.f - wsum) * Wp[b * NMEM + t] + ww;

    // --- M_n (float4, coalesced) ---
    const float4* M4 = (const float4*)(M + b * NMEM * WD);
    float4* Mn4 = (float4*)(Mn_out + b * NMEM * WD);
    const float4* es4 = (const float4*)es;
    const float4* vs4 = (const float4*)vs;
#pragma unroll
    for (int i = 0; i < 16; i++) {
        int idx4 = t + i * NMEM;       // 8192 float4 per batch
        int n = idx4 >> 4, w4 = idx4 & 15;
        float wwn = wws[n];
        float4 m4 = M4[idx4];
        float4 e4 = es4[w4];
        float4 v4 = vs4[w4];
        float4 o;
        o.x = m4.x * (1.f - wwn * e4.x) + wwn * v4.x;
        o.y = m4.y * (1.f - wwn * e4.y) + wwn * v4.y;
        o.z = m4.z * (1.f - wwn * e4.z) + wwn * v4.z;
        o.w = m4.w * (1.f - wwn * e4.w) + wwn * v4.w;
        Mn4[idx4] = o;
    }
}

// ---------------------------------------------------------------------------
// Link update + fused fwd/bwd partial reductions, 64x64 tiles, float4 I/O.
// grid (64 tiles, 64 batches), block 256
// ---------------------------------------------------------------------------
__global__ void link_kernel(const float* __restrict__ L, const float* __restrict__ Ww,
                            const float* __restrict__ Wp, const float* __restrict__ Wr,
                            float* __restrict__ Ln_out) {
    __shared__ __align__(16) float Ln_s[64][68];
    __shared__ float Wwi[64], Wwj[64], Wpj[64];
    __shared__ float Wri[64][4], Wrj[64][4];
    int b = blockIdx.y;
    int it = blockIdx.x >> 3, jt = blockIdx.x & 7;
    int i0 = it * 64, j0 = jt * 64;
    int t = threadIdx.x;
    if (t < 64) {
        Wwi[t] = Ww[b * NMEM + i0 + t];
        Wwj[t] = Ww[b * NMEM + j0 + t];
        Wpj[t] = Wp[b * NMEM + j0 + t];
    }
    {
        int n = t >> 2, r = t & 3;
        Wri[n][r] = Wr[(b * NMEM + i0 + n) * RH + r];
        Wrj[n][r] = Wr[(b * NMEM + j0 + n) * RH + r];
    }
    __syncthreads();
#pragma unroll
    for (int k = 0; k < 4; k++) {
        int e4 = t + k * 256;               // 1024 float4 in tile
        int il = e4 >> 4, j4 = (e4 & 15) * 4;
        long gidx = ((long)(b * NMEM + i0 + il)) * NMEM + j0 + j4;
        float4 l4 = *(const float4*)(L + gidx);
        float wwi = Wwi[il];
        float4 ln;
        ln.x = (1.f - wwi - Wwj[j4 + 0]) * l4.x + wwi * Wpj[j4 + 0];
        ln.y = (1.f - wwi - Wwj[j4 + 1]) * l4.y + wwi * Wpj[j4 + 1];
        ln.z = (1.f - wwi - Wwj[j4 + 2]) * l4.z + wwi * Wpj[j4 + 2];
        ln.w = (1.f - wwi - Wwj[j4 + 3]) * l4.w + wwi * Wpj[j4 + 3];
        if (it == jt) {
            if (il == j4 + 0) ln.x = 0.f;
            if (il == j4 + 1) ln.y = 0.f;
            if (il == j4 + 2) ln.z = 0.f;
            if (il == j4 + 3) ln.w = 0.f;
        }
        *(float4*)&Ln_s[il][j4] = ln;
        *(float4*)(Ln_out + gidx) = ln;
    }
    __syncthreads();
    {
        int il = t >> 2, r = t & 3;
        float accF = 0.f, accB = 0.f;
#pragma unroll
        for (int c = 0; c < 64; c++) {
            accF += Ln_s[il][c] * Wrj[c][r];   // fwd: row-reduction over j
            accB += Ln_s[c][il] * Wri[c][r];   // bwd: col-reduction over i
        }
        g_fwdpart[((b * 8 + jt) * NMEM + i0 + il) * RH + r] = accF;
        g_bwdpart[((b * 8 + it) * NMEM + j0 + il) * RH + r] = accB;
    }
}

// ---------------------------------------------------------------------------
// Fused: partial reduce + read content lookup + mode mix -> Wr_n
//        + read vectors + output projection. 64 blocks x 512 threads.
// ---------------------------------------------------------------------------
__global__ void read_fused_kernel(const float* __restrict__ Mn,
                                  const float* __restrict__ Wro,
                                  float* __restrict__ Wr_out,
                                  float* __restrict__ y_out) {
    __shared__ __align__(16) float fwd_s[NMEM * RH];   // 8KB
    __shared__ __align__(16) float bwd_s[NMEM * RH];   // 8KB
    __shared__ float Wrs[NMEM][RH];                    // 8KB
    __shared__ __align__(16) float nk[RH][WD];
    __shared__ float br[RH];
    __shared__ float m0s[RH], m1s[RH], m2s[RH];
    __shared__ float sb[16];
    __shared__ float part[512];
    __shared__ float rv[256];
    int b = blockIdx.x, t = threadIdx.x;
    const float* ifr = g_iface + (2 * b) * IFC;

    // reduce 8 partial tiles (float4)
    {
        float4 f4 = make_float4(0.f, 0.f, 0.f, 0.f);
        float4 b4 = make_float4(0.f, 0.f, 0.f, 0.f);
#pragma unroll
        for (int c = 0; c < 8; c++) {
            const float4* fp = (const float4*)(g_fwdpart + (b * 8 + c) * (NMEM * RH)) + t;
            const float4* bp = (const float4*)(g_bwdpart + (b * 8 + c) * (NMEM * RH)) + t;
            float4 fv = *fp, bv = *bp;
            f4.x += fv.x; f4.y += fv.y; f4.z += fv.z; f4.w += fv.w;
            b4.x += bv.x; b4.y += bv.y; b4.z += bv.z; b4.w += bv.w;
        }
        ((float4*)fwd_s)[t] = f4;
        ((float4*)bwd_s)[t] = b4;
    }
    if (t < RH * WD) {
        int r = t >> 6, w = t & 63;
        nk[r][w] = ifr[r * WD + w];
    }
    if (t >= 256 && t < 256 + RH) {
        int r = t - 256;
        br[r] = 1.f + softplusf_(ifr[256 + r]);
        float a = ifr[459 + r], bb = ifr[463 + r], c = ifr[467 + r];
        float mx = fmaxf(a, fmaxf(bb, c));
        float ea = expf(a - mx), eb = expf(bb - mx), ec = expf(c - mx);
        float s = ea + eb + ec;
        m0s[r] = ea / s; m1s[r] = eb / s; m2s[r] = ec / s;
    }
    __syncthreads();
    if (t < RH) {
        float s = 0.f;
        for (int w = 0; w < WD; w++) { float v = nk[t][w]; s += v * v; }
        float rn = 1.f / sqrtf(fmaxf(s, 1e-12f));
        for (int w = 0; w < WD; w++) nk[t][w] *= rn;
    }
    __syncthreads();

    // content lookup (4 heads, float4)
    const float4* m4p = (const float4*)(Mn + (b * NMEM + t) * WD);
    float d[RH] = {0.f, 0.f, 0.f, 0.f};
    float nrm = 0.f;
#pragma unroll
    for (int i = 0; i < 16; i++) {
        float4 m4 = m4p[i];
        nrm += m4.x * m4.x + m4.y * m4.y + m4.z * m4.z + m4.w * m4.w;
#pragma unroll
        for (int r = 0; r < RH; r++) {
            float4 k4 = ((const float4*)nk[r])[i];
            d[r] += m4.x * k4.x + m4.y * k4.y + m4.z * k4.z + m4.w * k4.w;
        }
    }
    float rn = 1.f / sqrtf(fmaxf(nrm, 1e-12f));
    float wl[RH];
#pragma unroll
    for (int r = 0; r < RH; r++) {
        float s = d[r] * rn * br[r];
        float mxv = blk_red_max(s, sb, t);
        float e = expf(s - mxv);
        float ssum = blk_red_sum(e, sb, t);
        wl[r] = e / ssum;
    }
#pragma unroll
    for (int r = 0; r < RH; r++) {
        float v = m0s[r] * bwd_s[t * RH + r] + m1s[r] * wl[r] + m2s[r] * fwd_s[t * RH + r];
        Wr_out[(b * NMEM + t) * RH + r] = v;
        Wrs[t][r] = v;
    }
    __syncthreads();

    // read vectors: rv[r*64+w] = sum_n Mn[n,w] * Wr[n,r]; all 512 threads
    {
        int half = t >> 8, tt = t & 255;
        int r = tt >> 6, w = tt & 63;
        int n0 = half * 256;
        float acc = 0.f;
#pragma unroll 8
        for (int n = 0; n < 256; n++)
            acc += Mn[(b * NMEM + n0 + n) * WD + w] * Wrs[n0 + n][r];
        part[t] = acc;
    }
    __syncthreads();
    if (t < 256) rv[t] = part[t] + part[256 + t];
    __syncthreads();
    // y = rv @ W_read_out ; all 512 threads (k-split)
    {
        int half = t >> 8, tt = t & 255;
        int k0 = half * 128;
        float ya = 0.f;
#pragma unroll 8
        for (int k = 0; k < 128; k++) ya += rv[k0 + k] * Wro[(k0 + k) * OUTD + tt];
        part[t] = ya;
    }
    __syncthreads();
    if (t < 256) y_out[b * OUTD + t] = part[t] + part[256 + t];
}

// ---------------------------------------------------------------------------
extern "C" void kernel_launch(void* const* d_in, const int* in_sizes, int n_in,
                              void* d_out, int out_size) {
    const float* inputs   = (const float*)d_in[0];
    const float* M        = (const float*)d_in[1];
    const float* usage    = (const float*)d_in[2];
    const float* L        = (const float*)d_in[3];
    const float* Wp       = (const float*)d_in[4];
    const float* W_read   = (const float*)d_in[5];
    const float* W_write  = (const float*)d_in[6];
    const float* h_ctrl   = (const float*)d_in[7];
    const float* W_iface  = (const float*)d_in[8];
    const float* W_rdout  = (const float*)d_in[9];
    const float* gru_k    = (const float*)d_in[10];
    const float* gru_rk   = (const float*)d_in[11];
    const float* gru_b    = (const float*)d_in[12];

    float* out = (float*)d_out;
    float* o_y    = out + OFF_Y;
    float* o_mn   = out + OFF_MN;
    float* o_use  = out + OFF_USAGE;
    float* o_ln   = out + OFF_LN;
    float* o_wp   = out + OFF_WP;
    float* o_wr   = out + OFF_WR;
    float* o_ww   = out + OFF_WW;
    float* o_hc   = out + OFF_HC;

    // 1) GRU mats mx & mh in one launch (64x64 tiles, z selects)
    gemm_gru<<<dim3((G3 + 63) / 64, 2, 2), 256>>>(inputs, h_ctrl, gru_k, gru_rk, gru_b);
    // 2) combine -> hc
    gru_combine<<<(128 * CD + 255) / 256, 256>>>(h_ctrl, o_hc);
    // 3) interface = hc @ W_interface (32x32 tiles for block count)
    gemm_iface<<<dim3((IFC + 31) / 32, 4), 128>>>(o_hc, W_iface);
    // 4) fused usage + alloc + write lookup + Ww + Wp + M_n (sort-free)
    memupdate_kernel<<<BSZ, NMEM>>>(W_read, W_write, usage, M, Wp,
                                    o_use, o_ww, o_wp, o_mn);
    // 5) link update fused with fwd/bwd partials
    link_kernel<<<dim3(64, BSZ), 256>>>(L, o_ww, Wp, W_read, o_ln);
    // 6) fused reduce + read lookup + Wr + read vectors + y
    read_fused_kernel<<<BSZ, NMEM>>>(o_mn, W_rdout, o_wr, o_y);
}

// round 7
// speedup vs baseline: 1.1247x; 1.1247x over previous
#include <cuda_runtime.h>
#include <math.h>

// Problem dims
#define BSZ   64
#define NMEM  512
#define WD    64
#define RH    4
#define OUTD  256
#define IND   256
#define IFC   471     // interface size
#define CD    727     // controller dim
#define G3    2181    // 3*CD

// Output layout offsets (concatenated flattened tuple, f32)
#define OFF_Y      0
#define OFF_MN     16384
#define OFF_USAGE  2113536
#define OFF_LN     2146304
#define OFF_WP     18923520
#define OFF_WR     18956288
#define OFF_WW     19087360
#define OFF_HC     19120128

// Scratch (no cudaMalloc allowed)
__device__ float g_mx[128 * G3];
__device__ float g_mh[128 * G3];
__device__ float g_iface[128 * IFC];
__device__ __align__(16) float g_fwdpart[BSZ * 8 * NMEM * RH];
__device__ __align__(16) float g_bwdpart[BSZ * 8 * NMEM * RH];

__device__ __forceinline__ float sigmoidf_(float x) { return 1.f / (1.f + expf(-x)); }
__device__ __forceinline__ float softplusf_(float x) { return fmaxf(x, 0.f) + log1pf(expf(-fabsf(x))); }

// Block-wide reductions for 512 threads: shuffle within warp + 16-slot shared.
__device__ __forceinline__ float blk_red_max(float v, float* sb, int t) {
#pragma unroll
    for (int o = 16; o; o >>= 1) v = fmaxf(v, __shfl_xor_sync(0xffffffffu, v, o));
    __syncthreads();
    if ((t & 31) == 0) sb[t >> 5] = v;
    __syncthreads();
    float r = sb[0];
#pragma unroll
    for (int i = 1; i < 16; i++) r = fmaxf(r, sb[i]);
    return r;
}
__device__ __forceinline__ float blk_red_sum(float v, float* sb, int t) {
#pragma unroll
    for (int o = 16; o; o >>= 1) v += __shfl_xor_sync(0xffffffffu, v, o);
    __syncthreads();
    if ((t & 31) == 0) sb[t >> 5] = v;
    __syncthreads();
    float r = 0.f;
#pragma unroll
    for (int i = 0; i < 16; i++) r += sb[i];
    return r;
}

// ---------------------------------------------------------------------------
// Register-tiled GEMM body (32x32 tile, 128 threads, 2x4 micro) — the config
// measured fastest (Round 4). C[M,N] = A[M,K] @ B[K,N] (+bias).
// ---------------------------------------------------------------------------
__device__ __forceinline__ void gemm_body(const float* __restrict__ A,
                                          const float* __restrict__ B,
                                          const float* __restrict__ bias,
                                          float* __restrict__ C,
                                          int N, int K) {
    __shared__ __align__(16) float Ast[32][34];   // transposed A tile, padded
    __shared__ __align__(16) float Bs[32][32];
    int t = threadIdx.x;            // 128 threads
    int m0 = blockIdx.y * 32;
    int n0 = blockIdx.x * 32;
    if (n0 >= N) return;
    int tx = t & 7;                 // col group (4 cols)
    int ty = t >> 3;                // row group (2 rows)
    float acc[2][4] = {{0.f,0.f,0.f,0.f},{0.f,0.f,0.f,0.f}};

    for (int k0 = 0; k0 < K; k0 += 32) {
#pragma unroll
        for (int i = 0; i < 8; i++) {
            int e = t + i * 128;
            int k = e & 31, m = e >> 5;
            float v = 0.f;
            if (k0 + k < K) v = A[(m0 + m) * K + k0 + k];
            Ast[k][m] = v;
        }
#pragma unroll
        for (int i = 0; i < 8; i++) {
            int e = t + i * 128;
            int c = e & 31, k = e >> 5;
            float v = 0.f;
            if (k0 + k < K && n0 + c < N) v = B[(k0 + k) * N + n0 + c];
            Bs[k][c] = v;
        }
        __syncthreads();
#pragma unroll
        for (int kk = 0; kk < 32; kk++) {
            float2 a2 = *(const float2*)&Ast[kk][ty * 2];
            float4 b4 = *(const float4*)&Bs[kk][tx * 4];
            acc[0][0] += a2.x * b4.x; acc[0][1] += a2.x * b4.y;
            acc[0][2] += a2.x * b4.z; acc[0][3] += a2.x * b4.w;
            acc[1][0] += a2.y * b4.x; acc[1][1] += a2.y * b4.y;
            acc[1][2] += a2.y * b4.z; acc[1][3] += a2.y * b4.w;
        }
        __syncthreads();
    }
#pragma unroll
    for (int i = 0; i < 2; i++) {
        int row = m0 + ty * 2 + i;
#pragma unroll
        for (int j = 0; j < 4; j++) {
            int col = n0 + tx * 4 + j;
            if (col < N) {
                float v = acc[i][j];
                if (bias) v += bias[col];
                C[row * N + col] = v;
            }
        }
    }
}

// Dual launch: z=0 -> mx = X @ gru_k + b0 ; z=1 -> mh = H @ gru_rk + b1
__global__ void gemm_gru(const float* __restrict__ X, const float* __restrict__ H,
                         const float* __restrict__ gk, const float* __restrict__ grk,
                         const float* __restrict__ gb) {
    if (blockIdx.z == 0) gemm_body(X, gk, gb, g_mx, G3, IND);
    else                 gemm_body(H, grk, gb + G3, g_mh, G3, CD);
}

__global__ void gemm_iface(const float* __restrict__ hc, const float* __restrict__ Wif) {
    gemm_body(hc, Wif, nullptr, g_iface, IFC, CD);
}

// ---------------------------------------------------------------------------
// GRU combine: c = z*h + (1-z)*gelu(xh + r*rh)
// ---------------------------------------------------------------------------
__global__ void gru_combine(const float* __restrict__ h, float* __restrict__ hc_out) {
    int idx = blockIdx.x * blockDim.x + threadIdx.x;
    if (idx >= 128 * CD) return;
    int row = idx / CD, j = idx % CD;
    const float* mx = g_mx + row * G3;
    const float* mh = g_mh + row * G3;
    float z = sigmoidf_(mx[j] + mh[j]);
    float r = sigmoidf_(mx[CD + j] + mh[CD + j]);
    float hin = mx[2 * CD + j] + r * mh[2 * CD + j];
    float hh = hin * normcdff(hin);   // exact gelu
    float hv = h[idx];
    hc_out[idx] = z * hv + (1.f - z) * hh;
}

// ---------------------------------------------------------------------------
// Fused per-batch memory update (sort-free, strict-less float4 alloc loop)
// 64 blocks x 512 threads
// ---------------------------------------------------------------------------
__global__ void memupdate_kernel(const float* __restrict__ W_read,
                                 const float* __restrict__ W_write,
                                 const float* __restrict__ usage,
                                 const float* __restrict__ M,
                                 const float* __restrict__ Wp,
                                 float* __restrict__ usage_out,
                                 float* __restrict__ Ww_out,
                                 float* __restrict__ Wp_out,
                                 float* __restrict__ Mn_out) {
    __shared__ __align__(16) float us[NMEM];
    __shared__ float wws[NMEM];
    __shared__ __align__(16) float nk[WD];
    __shared__ __align__(16) float es[WD];
    __shared__ __align__(16) float vs[WD];
    __shared__ float keyn[WD];
    __shared__ float sc[4];
    __shared__ float sb[16];
    int b = blockIdx.x, t = threadIdx.x;
    const float* ifw = g_iface + (2 * b + 1) * IFC;

    // --- usage_n ---
    float4 wr4 = *(const float4*)(W_read + (b * NMEM + t) * RH);
    float ret = (1.f - sigmoidf_(ifw[453]) * wr4.x)
              * (1.f - sigmoidf_(ifw[454]) * wr4.y)
              * (1.f - sigmoidf_(ifw[455]) * wr4.z)
              * (1.f - sigmoidf_(ifw[456]) * wr4.w);
    float u = usage[b * NMEM + t], w = W_write[b * NMEM + t];
    float un = (u + w - u * w) * ret;
    usage_out[b * NMEM + t] = un;
    us[t] = un;
    if (t < WD) {
        es[t] = sigmoidf_(ifw[325 + t]);
        vs[t] = ifw[389 + t];
        float kv = ifw[260 + t];
        keyn[t] = kv * kv;
    }
    __syncthreads();
    if (t == 0) {
        float s = 0.f;
        for (int i = 0; i < WD; i++) s += keyn[i];
        sc[0] = 1.f / sqrtf(fmaxf(s, 1e-12f));
        sc[1] = 1.f + softplusf_(ifw[324]);   // b_write
        sc[2] = sigmoidf_(ifw[457]);          // alloc_g
        sc[3] = sigmoidf_(ifw[458]);          // write_g
    }

    // --- W_alloc[n] = (1-u[n]) * prod_{u[m] < u[n]} u[m]   (strict less:
    //     self is excluded automatically since us[t]==un; continuous data
    //     has no cross-element ties). float4 LDS, broadcast-friendly.
    float p = 1.f;
    {
        const float4* us4 = (const float4*)us;
#pragma unroll 4
        for (int i = 0; i < NMEM / 4; i++) {
            float4 u4 = us4[i];
            p *= (u4.x < un) ? u4.x : 1.f;
            p *= (u4.y < un) ? u4.y : 1.f;
            p *= (u4.z < un) ? u4.z : 1.f;
            p *= (u4.w < un) ? u4.w : 1.f;
        }
    }
    float walloc = (1.f - un) * p;
    __syncthreads();
    if (t < WD) nk[t] = ifw[260 + t] * sc[0];
    __syncthreads();

    // --- write content lookup (float4) ---
    const float4* m4p = (const float4*)(M + (b * NMEM + t) * WD);
    const float4* nk4 = (const float4*)nk;
    float dot = 0.f, nrm = 0.f;
#pragma unroll
    for (int i = 0; i < 16; i++) {
        float4 m4 = m4p[i];
        float4 k4 = nk4[i];
        dot += m4.x * k4.x + m4.y * k4.y + m4.z * k4.z + m4.w * k4.w;
        nrm += m4.x * m4.x + m4.y * m4.y + m4.z * m4.z + m4.w * m4.w;
    }
    float s = dot * (1.f / sqrtf(fmaxf(nrm, 1e-12f))) * sc[1];
    float mxv = blk_red_max(s, sb, t);
    float e = expf(s - mxv);
    float ssum = blk_red_sum(e, sb, t);
    float wl = e / ssum;

    float ww = sc[3] * (sc[2] * walloc + (1.f - sc[2]) * wl);
    Ww_out[b * NMEM + t] = ww;
    wws[t] = ww;
    float wsum = blk_red_sum(ww, sb, t);   // barriers inside make wws visible
    // --- precedence ---
    Wp_out[b * NMEM + t] = (1.f - wsum) * Wp[b * NMEM + t] + ww;

    // --- M_n (float4, coalesced) ---
    const float4* M4 = (const float4*)(M + b * NMEM * WD);
    float4* Mn4 = (float4*)(Mn_out + b * NMEM * WD);
    const float4* es4 = (const float4*)es;
    const float4* vs4 = (const float4*)vs;
#pragma unroll
    for (int i = 0; i < 16; i++) {
        int idx4 = t + i * NMEM;       // 8192 float4 per batch
        int n = idx4 >> 4, w4 = idx4 & 15;
        float wwn = wws[n];
        float4 m4 = M4[idx4];
        float4 e4 = es4[w4];
        float4 v4 = vs4[w4];
        float4 o;
        o.x = m4.x * (1.f - wwn * e4.x) + wwn * v4.x;
        o.y = m4.y * (1.f - wwn * e4.y) + wwn * v4.y;
        o.z = m4.z * (1.f - wwn * e4.z) + wwn * v4.z;
        o.w = m4.w * (1.f - wwn * e4.w) + wwn * v4.w;
        Mn4[idx4] = o;
    }
}

// ---------------------------------------------------------------------------
// Link update + fused fwd/bwd partial reductions, 64x64 tiles, float4 I/O.
// grid (64 tiles, 64 batches), block 256
// ---------------------------------------------------------------------------
__global__ void link_kernel(const float* __restrict__ L, const float* __restrict__ Ww,
                            const float* __restrict__ Wp, const float* __restrict__ Wr,
                            float* __restrict__ Ln_out) {
    __shared__ __align__(16) float Ln_s[64][68];
    __shared__ float Wwi[64], Wwj[64], Wpj[64];
    __shared__ float Wri[64][4], Wrj[64][4];
    int b = blockIdx.y;
    int it = blockIdx.x >> 3, jt = blockIdx.x & 7;
    int i0 = it * 64, j0 = jt * 64;
    int t = threadIdx.x;
    if (t < 64) {
        Wwi[t] = Ww[b * NMEM + i0 + t];
        Wwj[t] = Ww[b * NMEM + j0 + t];
        Wpj[t] = Wp[b * NMEM + j0 + t];
    }
    {
        int n = t >> 2, r = t & 3;
        Wri[n][r] = Wr[(b * NMEM + i0 + n) * RH + r];
        Wrj[n][r] = Wr[(b * NMEM + j0 + n) * RH + r];
    }
    __syncthreads();
#pragma unroll
    for (int k = 0; k < 4; k++) {
        int e4 = t + k * 256;               // 1024 float4 in tile
        int il = e4 >> 4, j4 = (e4 & 15) * 4;
        long gidx = ((long)(b * NMEM + i0 + il)) * NMEM + j0 + j4;
        float4 l4 = *(const float4*)(L + gidx);
        float wwi = Wwi[il];
        float4 ln;
        ln.x = (1.f - wwi - Wwj[j4 + 0]) * l4.x + wwi * Wpj[j4 + 0];
        ln.y = (1.f - wwi - Wwj[j4 + 1]) * l4.y + wwi * Wpj[j4 + 1];
        ln.z = (1.f - wwi - Wwj[j4 + 2]) * l4.z + wwi * Wpj[j4 + 2];
        ln.w = (1.f - wwi - Wwj[j4 + 3]) * l4.w + wwi * Wpj[j4 + 3];
        if (it == jt) {
            if (il == j4 + 0) ln.x = 0.f;
            if (il == j4 + 1) ln.y = 0.f;
            if (il == j4 + 2) ln.z = 0.f;
            if (il == j4 + 3) ln.w = 0.f;
        }
        *(float4*)&Ln_s[il][j4] = ln;
        *(float4*)(Ln_out + gidx) = ln;
    }
    __syncthreads();
    {
        int il = t >> 2, r = t & 3;
        float accF = 0.f, accB = 0.f;
#pragma unroll
        for (int c = 0; c < 64; c++) {
            accF += Ln_s[il][c] * Wrj[c][r];   // fwd: row-reduction over j
            accB += Ln_s[c][il] * Wri[c][r];   // bwd: col-reduction over i
        }
        g_fwdpart[((b * 8 + jt) * NMEM + i0 + il) * RH + r] = accF;
        g_bwdpart[((b * 8 + it) * NMEM + j0 + il) * RH + r] = accB;
    }
}

// ---------------------------------------------------------------------------
// Fused: partial reduce + read content lookup + mode mix -> Wr_n
//        + read vectors + output projection. 64 blocks x 512 threads.
// ---------------------------------------------------------------------------
__global__ void read_fused_kernel(const float* __restrict__ Mn,
                                  const float* __restrict__ Wro,
                                  float* __restrict__ Wr_out,
                                  float* __restrict__ y_out) {
    __shared__ __align__(16) float fwd_s[NMEM * RH];   // 8KB
    __shared__ __align__(16) float bwd_s[NMEM * RH];   // 8KB
    __shared__ float Wrs[NMEM][RH];                    // 8KB
    __shared__ __align__(16) float nk[RH][WD];
    __shared__ float br[RH];
    __shared__ float m0s[RH], m1s[RH], m2s[RH];
    __shared__ float sb[16];
    __shared__ float part[512];
    __shared__ float rv[256];
    int b = blockIdx.x, t = threadIdx.x;
    const float* ifr = g_iface + (2 * b) * IFC;

    // reduce 8 partial tiles (float4)
    {
        float4 f4 = make_float4(0.f, 0.f, 0.f, 0.f);
        float4 b4 = make_float4(0.f, 0.f, 0.f, 0.f);
#pragma unroll
        for (int c = 0; c < 8; c++) {
            const float4* fp = (const float4*)(g_fwdpart + (b * 8 + c) * (NMEM * RH)) + t;
            const float4* bp = (const float4*)(g_bwdpart + (b * 8 + c) * (NMEM * RH)) + t;
            float4 fv = *fp, bv = *bp;
            f4.x += fv.x; f4.y += fv.y; f4.z += fv.z; f4.w += fv.w;
            b4.x += bv.x; b4.y += bv.y; b4.z += bv.z; b4.w += bv.w;
        }
        ((float4*)fwd_s)[t] = f4;
        ((float4*)bwd_s)[t] = b4;
    }
    if (t < RH * WD) {
        int r = t >> 6, w = t & 63;
        nk[r][w] = ifr[r * WD + w];
    }
    if (t >= 256 && t < 256 + RH) {
        int r = t - 256;
        br[r] = 1.f + softplusf_(ifr[256 + r]);
        float a = ifr[459 + r], bb = ifr[463 + r], c = ifr[467 + r];
        float mx = fmaxf(a, fmaxf(bb, c));
        float ea = expf(a - mx), eb = expf(bb - mx), ec = expf(c - mx);
        float s = ea + eb + ec;
        m0s[r] = ea / s; m1s[r] = eb / s; m2s[r] = ec / s;
    }
    __syncthreads();
    if (t < RH) {
        float s = 0.f;
        for (int w = 0; w < WD; w++) { float v = nk[t][w]; s += v * v; }
        float rn = 1.f / sqrtf(fmaxf(s, 1e-12f));
        for (int w = 0; w < WD; w++) nk[t][w] *= rn;
    }
    __syncthreads();

    // content lookup (4 heads, float4)
    const float4* m4p = (const float4*)(Mn + (b * NMEM + t) * WD);
    float d[RH] = {0.f, 0.f, 0.f, 0.f};
    float nrm = 0.f;
#pragma unroll
    for (int i = 0; i < 16; i++) {
        float4 m4 = m4p[i];
        nrm += m4.x * m4.x + m4.y * m4.y + m4.z * m4.z + m4.w * m4.w;
#pragma unroll
        for (int r = 0; r < RH; r++) {
            float4 k4 = ((const float4*)nk[r])[i];
            d[r] += m4.x * k4.x + m4.y * k4.y + m4.z * k4.z + m4.w * k4.w;
        }
    }
    float rn = 1.f / sqrtf(fmaxf(nrm, 1e-12f));
    float wl[RH];
#pragma unroll
    for (int r = 0; r < RH; r++) {
        float s = d[r] * rn * br[r];
        float mxv = blk_red_max(s, sb, t);
        float e = expf(s - mxv);
        float ssum = blk_red_sum(e, sb, t);
        wl[r] = e / ssum;
    }
#pragma unroll
    for (int r = 0; r < RH; r++) {
        float v = m0s[r] * bwd_s[t * RH + r] + m1s[r] * wl[r] + m2s[r] * fwd_s[t * RH + r];
        Wr_out[(b * NMEM + t) * RH + r] = v;
        Wrs[t][r] = v;
    }
    __syncthreads();

    // read vectors: rv[r*64+w] = sum_n Mn[n,w] * Wr[n,r]; all 512 threads
    {
        int half = t >> 8, tt = t & 255;
        int r = tt >> 6, w = tt & 63;
        int n0 = half * 256;
        float acc = 0.f;
#pragma unroll 8
        for (int n = 0; n < 256; n++)
            acc += Mn[(b * NMEM + n0 + n) * WD + w] * Wrs[n0 + n][r];
        part[t] = acc;
    }
    __syncthreads();
    if (t < 256) rv[t] = part[t] + part[256 + t];
    __syncthreads();
    // y = rv @ W_read_out ; all 512 threads (k-split)
    {
        int half = t >> 8, tt = t & 255;
        int k0 = half * 128;
        float ya = 0.f;
#pragma unroll 8
        for (int k = 0; k < 128; k++) ya += rv[k0 + k] * Wro[(k0 + k) * OUTD + tt];
        part[t] = ya;
    }
    __syncthreads();
    if (t < 256) y_out[b * OUTD + t] = part[t] + part[256 + t];
}

// ---------------------------------------------------------------------------
extern "C" void kernel_launch(void* const* d_in, const int* in_sizes, int n_in,
                              void* d_out, int out_size) {
    const float* inputs   = (const float*)d_in[0];
    const float* M        = (const float*)d_in[1];
    const float* usage    = (const float*)d_in[2];
    const float* L        = (const float*)d_in[3];
    const float* Wp       = (const float*)d_in[4];
    const float* W_read   = (const float*)d_in[5];
    const float* W_write  = (const float*)d_in[6];
    const float* h_ctrl   = (const float*)d_in[7];
    const float* W_iface  = (const float*)d_in[8];
    const float* W_rdout  = (const float*)d_in[9];
    const float* gru_k    = (const float*)d_in[10];
    const float* gru_rk   = (const float*)d_in[11];
    const float* gru_b    = (const float*)d_in[12];

    float* out = (float*)d_out;
    float* o_y    = out + OFF_Y;
    float* o_mn   = out + OFF_MN;
    float* o_use  = out + OFF_USAGE;
    float* o_ln   = out + OFF_LN;
    float* o_wp   = out + OFF_WP;
    float* o_wr   = out + OFF_WR;
    float* o_ww   = out + OFF_WW;
    float* o_hc   = out + OFF_HC;

    // 1) GRU mats mx & mh in one launch (32x32 tiles — measured fastest)
    gemm_gru<<<dim3((G3 + 31) / 32, 4, 2), 128>>>(inputs, h_ctrl, gru_k, gru_rk, gru_b);
    // 2) combine -> hc
    gru_combine<<<(128 * CD + 255) / 256, 256>>>(h_ctrl, o_hc);
    // 3) interface = hc @ W_interface
    gemm_iface<<<dim3((IFC + 31) / 32, 4), 128>>>(o_hc, W_iface);
    // 4) fused usage + alloc + write lookup + Ww + Wp + M_n (sort-free)
    memupdate_kernel<<<BSZ, NMEM>>>(W_read, W_write, usage, M, Wp,
                                    o_use, o_ww, o_wp, o_mn);
    // 5) link update fused with fwd/bwd partials
    link_kernel<<<dim3(64, BSZ), 256>>>(L, o_ww, Wp, W_read, o_ln);
    // 6) fused reduce + read lookup + Wr + read vectors + y
    read_fused_kernel<<<BSZ, NMEM>>>(o_mn, W_rdout, o_wr, o_y);
}

// round 8
// speedup vs baseline: 1.1559x; 1.0278x over previous
#include <cuda_runtime.h>
#include <math.h>

// Problem dims
#define BSZ   64
#define NMEM  512
#define WD    64
#define RH    4
#define OUTD  256
#define IND   256
#define IFC   471     // interface size
#define CD    727     // controller dim
#define G3    2181    // 3*CD

// Output layout offsets (concatenated flattened tuple, f32)
#define OFF_Y      0
#define OFF_MN     16384
#define OFF_USAGE  2113536
#define OFF_LN     2146304
#define OFF_WP     18923520
#define OFF_WR     18956288
#define OFF_WW     19087360
#define OFF_HC     19120128

// Scratch (no cudaMalloc allowed)
__device__ float g_mx[128 * G3];
__device__ float g_mh[128 * G3];
__device__ float g_iface[128 * IFC];
__device__ __align__(16) float g_fwdpart[BSZ * 8 * NMEM * RH];
__device__ __align__(16) float g_bwdpart[BSZ * 8 * NMEM * RH];

__device__ __forceinline__ float sigmoidf_(float x) { return 1.f / (1.f + expf(-x)); }
__device__ __forceinline__ float softplusf_(float x) { return fmaxf(x, 0.f) + log1pf(expf(-fabsf(x))); }

// Block-wide reductions for 512 threads: shuffle within warp + 16-slot shared.
__device__ __forceinline__ float blk_red_max(float v, float* sb, int t) {
#pragma unroll
    for (int o = 16; o; o >>= 1) v = fmaxf(v, __shfl_xor_sync(0xffffffffu, v, o));
    __syncthreads();
    if ((t & 31) == 0) sb[t >> 5] = v;
    __syncthreads();
    float r = sb[0];
#pragma unroll
    for (int i = 1; i < 16; i++) r = fmaxf(r, sb[i]);
    return r;
}
__device__ __forceinline__ float blk_red_sum(float v, float* sb, int t) {
#pragma unroll
    for (int o = 16; o; o >>= 1) v += __shfl_xor_sync(0xffffffffu, v, o);
    __syncthreads();
    if ((t & 31) == 0) sb[t >> 5] = v;
    __syncthreads();
    float r = 0.f;
#pragma unroll
    for (int i = 0; i < 16; i++) r += sb[i];
    return r;
}

// ---------------------------------------------------------------------------
// Register-tiled GEMM body (32x32 tile, 128 threads, 2x4 micro) — the config
// measured fastest. C[M,N] = A[M,K] @ B[K,N] (+bias).
// ---------------------------------------------------------------------------
__device__ __forceinline__ void gemm_body(const float* __restrict__ A,
                                          const float* __restrict__ B,
                                          const float* __restrict__ bias,
                                          float* __restrict__ C,
                                          int N, int K) {
    __shared__ __align__(16) float Ast[32][34];   // transposed A tile, padded
    __shared__ __align__(16) float Bs[32][32];
    int t = threadIdx.x;            // 128 threads
    int m0 = blockIdx.y * 32;
    int n0 = blockIdx.x * 32;
    if (n0 >= N) return;
    int tx = t & 7;                 // col group (4 cols)
    int ty = t >> 3;                // row group (2 rows)
    float acc[2][4] = {{0.f,0.f,0.f,0.f},{0.f,0.f,0.f,0.f}};

    for (int k0 = 0; k0 < K; k0 += 32) {
#pragma unroll
        for (int i = 0; i < 8; i++) {
            int e = t + i * 128;
            int k = e & 31, m = e >> 5;
            float v = 0.f;
            if (k0 + k < K) v = A[(m0 + m) * K + k0 + k];
            Ast[k][m] = v;
        }
#pragma unroll
        for (int i = 0; i < 8; i++) {
            int e = t + i * 128;
            int c = e & 31, k = e >> 5;
            float v = 0.f;
            if (k0 + k < K && n0 + c < N) v = B[(k0 + k) * N + n0 + c];
            Bs[k][c] = v;
        }
        __syncthreads();
#pragma unroll
        for (int kk = 0; kk < 32; kk++) {
            float2 a2 = *(const float2*)&Ast[kk][ty * 2];
            float4 b4 = *(const float4*)&Bs[kk][tx * 4];
            acc[0][0] += a2.x * b4.x; acc[0][1] += a2.x * b4.y;
            acc[0][2] += a2.x * b4.z; acc[0][3] += a2.x * b4.w;
            acc[1][0] += a2.y * b4.x; acc[1][1] += a2.y * b4.y;
            acc[1][2] += a2.y * b4.z; acc[1][3] += a2.y * b4.w;
        }
        __syncthreads();
    }
#pragma unroll
    for (int i = 0; i < 2; i++) {
        int row = m0 + ty * 2 + i;
#pragma unroll
        for (int j = 0; j < 4; j++) {
            int col = n0 + tx * 4 + j;
            if (col < N) {
                float v = acc[i][j];
                if (bias) v += bias[col];
                C[row * N + col] = v;
            }
        }
    }
}

// Dual launch: z=0 -> mx = X @ gru_k + b0 ; z=1 -> mh = H @ gru_rk + b1
__global__ void gemm_gru(const float* __restrict__ X, const float* __restrict__ H,
                         const float* __restrict__ gk, const float* __restrict__ grk,
                         const float* __restrict__ gb) {
    if (blockIdx.z == 0) gemm_body(X, gk, gb, g_mx, G3, IND);
    else                 gemm_body(H, grk, gb + G3, g_mh, G3, CD);
}

__global__ void gemm_iface(const float* __restrict__ hc, const float* __restrict__ Wif) {
    gemm_body(hc, Wif, nullptr, g_iface, IFC, CD);
}

// ---------------------------------------------------------------------------
// GRU combine: c = z*h + (1-z)*gelu(xh + r*rh)
// ---------------------------------------------------------------------------
__global__ void gru_combine(const float* __restrict__ h, float* __restrict__ hc_out) {
    int idx = blockIdx.x * blockDim.x + threadIdx.x;
    if (idx >= 128 * CD) return;
    int row = idx / CD, j = idx % CD;
    const float* mx = g_mx + row * G3;
    const float* mh = g_mh + row * G3;
    float z = sigmoidf_(mx[j] + mh[j]);
    float r = sigmoidf_(mx[CD + j] + mh[CD + j]);
    float hin = mx[2 * CD + j] + r * mh[2 * CD + j];
    float hh = hin * normcdff(hin);   // exact gelu
    float hv = h[idx];
    hc_out[idx] = z * hv + (1.f - z) * hh;
}

// ---------------------------------------------------------------------------
// Fused per-batch memory update (sort-free, ILP-split alloc product).
// M_n moved into link launch. 64 blocks x 512 threads.
// ---------------------------------------------------------------------------
__global__ void memupdate_kernel(const float* __restrict__ W_read,
                                 const float* __restrict__ W_write,
                                 const float* __restrict__ usage,
                                 const float* __restrict__ M,
                                 const float* __restrict__ Wp,
                                 float* __restrict__ usage_out,
                                 float* __restrict__ Ww_out,
                                 float* __restrict__ Wp_out) {
    __shared__ __align__(16) float us[NMEM];
    __shared__ __align__(16) float nk[WD];
    __shared__ float keyn[WD];
    __shared__ float sc[4];
    __shared__ float sb[16];
    int b = blockIdx.x, t = threadIdx.x;
    const float* ifw = g_iface + (2 * b + 1) * IFC;

    // --- usage_n ---
    float4 wr4 = *(const float4*)(W_read + (b * NMEM + t) * RH);
    float ret = (1.f - sigmoidf_(ifw[453]) * wr4.x)
              * (1.f - sigmoidf_(ifw[454]) * wr4.y)
              * (1.f - sigmoidf_(ifw[455]) * wr4.z)
              * (1.f - sigmoidf_(ifw[456]) * wr4.w);
    float u = usage[b * NMEM + t], w = W_write[b * NMEM + t];
    float un = (u + w - u * w) * ret;
    usage_out[b * NMEM + t] = un;
    us[t] = un;
    if (t < WD) {
        float kv = ifw[260 + t];
        keyn[t] = kv * kv;
    }
    __syncthreads();
    if (t == 0) {
        float s = 0.f;
        for (int i = 0; i < WD; i++) s += keyn[i];
        sc[0] = 1.f / sqrtf(fmaxf(s, 1e-12f));
        sc[1] = 1.f + softplusf_(ifw[324]);   // b_write
        sc[2] = sigmoidf_(ifw[457]);          // alloc_g
        sc[3] = sigmoidf_(ifw[458]);          // write_g
    }

    // --- W_alloc[n] = (1-u[n]) * prod_{u[m] < u[n]} u[m]
    //     4 independent product chains (one per float4 lane) for ILP.
    float p0 = 1.f, p1 = 1.f, p2 = 1.f, p3 = 1.f;
    {
        const float4* us4 = (const float4*)us;
#pragma unroll 4
        for (int i = 0; i < NMEM / 4; i++) {
            float4 u4 = us4[i];
            p0 *= (u4.x < un) ? u4.x : 1.f;
            p1 *= (u4.y < un) ? u4.y : 1.f;
            p2 *= (u4.z < un) ? u4.z : 1.f;
            p3 *= (u4.w < un) ? u4.w : 1.f;
        }
    }
    float walloc = (1.f - un) * ((p0 * p1) * (p2 * p3));
    __syncthreads();
    if (t < WD) nk[t] = ifw[260 + t] * sc[0];
    __syncthreads();

    // --- write content lookup (float4) ---
    const float4* m4p = (const float4*)(M + (b * NMEM + t) * WD);
    const float4* nk4 = (const float4*)nk;
    float dot = 0.f, nrm = 0.f;
#pragma unroll
    for (int i = 0; i < 16; i++) {
        float4 m4 = m4p[i];
        float4 k4 = nk4[i];
        dot += m4.x * k4.x + m4.y * k4.y + m4.z * k4.z + m4.w * k4.w;
        nrm += m4.x * m4.x + m4.y * m4.y + m4.z * m4.z + m4.w * m4.w;
    }
    float s = dot * (1.f / sqrtf(fmaxf(nrm, 1e-12f))) * sc[1];
    float mxv = blk_red_max(s, sb, t);
    float e = expf(s - mxv);
    float ssum = blk_red_sum(e, sb, t);
    float wl = e / ssum;

    float ww = sc[3] * (sc[2] * walloc + (1.f - sc[2]) * wl);
    Ww_out[b * NMEM + t] = ww;
    float wsum = blk_red_sum(ww, sb, t);
    // --- precedence ---
    Wp_out[b * NMEM + t] = (1.f - wsum) * Wp[b * NMEM + t] + ww;
}

// ---------------------------------------------------------------------------
// Link update + fused fwd/bwd partials (tiles 0..63) + M_n chunks (64..67).
// grid (68, 64 batches), block 256
// ---------------------------------------------------------------------------
__global__ void link_kernel(const float* __restrict__ L, const float* __restrict__ Ww,
                            const float* __restrict__ Wp, const float* __restrict__ Wr,
                            const float* __restrict__ M, float* __restrict__ Mn_out,
                            float* __restrict__ Ln_out) {
    __shared__ __align__(16) float Ln_s[64][68];
    __shared__ float Wwi[64], Wwj[64], Wpj[64];
    __shared__ float Wri[64][4], Wrj[64][4];
    int b = blockIdx.y;
    int t = threadIdx.x;

    if (blockIdx.x >= 64) {
        // ---- M_n chunk: 128 rows of this batch ----
        int n0 = (blockIdx.x - 64) * 128;
        const float* ifw = g_iface + (2 * b + 1) * IFC;
        // reuse first shared rows as scratch
        float* es_ = &Ln_s[0][0];          // 64
        float* vs_ = &Ln_s[1][0];          // 64
        float* wws_ = &Ln_s[2][0];         // 128 (spans rows 2..3 region ok: row stride 68)
        if (t < WD) { es_[t] = sigmoidf_(ifw[325 + t]); vs_[t] = ifw[389 + t]; }
        if (t >= 64 && t < 192) wws_[t - 64] = Ww[b * NMEM + n0 + t - 64];
        __syncthreads();
        const float4* M4 = (const float4*)(M + (b * NMEM + n0) * WD);
        float4* Mn4 = (float4*)(Mn_out + (b * NMEM + n0) * WD);
#pragma unroll
        for (int i = 0; i < 8; i++) {
            int idx4 = t + i * 256;        // 2048 float4 in chunk
            int n = idx4 >> 4, w4 = (idx4 & 15) * 4;
            float wwn = wws_[n];
            float4 m4 = M4[idx4];
            float4 o;
            o.x = m4.x * (1.f - wwn * es_[w4 + 0]) + wwn * vs_[w4 + 0];
            o.y = m4.y * (1.f - wwn * es_[w4 + 1]) + wwn * vs_[w4 + 1];
            o.z = m4.z * (1.f - wwn * es_[w4 + 2]) + wwn * vs_[w4 + 2];
            o.w = m4.w * (1.f - wwn * es_[w4 + 3]) + wwn * vs_[w4 + 3];
            Mn4[idx4] = o;
        }
        return;
    }

    int it = blockIdx.x >> 3, jt = blockIdx.x & 7;
    int i0 = it * 64, j0 = jt * 64;
    if (t < 64) {
        Wwi[t] = Ww[b * NMEM + i0 + t];
        Wwj[t] = Ww[b * NMEM + j0 + t];
        Wpj[t] = Wp[b * NMEM + j0 + t];
    }
    {
        int n = t >> 2, r = t & 3;
        Wri[n][r] = Wr[(b * NMEM + i0 + n) * RH + r];
        Wrj[n][r] = Wr[(b * NMEM + j0 + n) * RH + r];
    }
    __syncthreads();
#pragma unroll
    for (int k = 0; k < 4; k++) {
        int e4 = t + k * 256;               // 1024 float4 in tile
        int il = e4 >> 4, j4 = (e4 & 15) * 4;
        long gidx = ((long)(b * NMEM + i0 + il)) * NMEM + j0 + j4;
        float4 l4 = *(const float4*)(L + gidx);
        float wwi = Wwi[il];
        float4 ln;
        ln.x = (1.f - wwi - Wwj[j4 + 0]) * l4.x + wwi * Wpj[j4 + 0];
        ln.y = (1.f - wwi - Wwj[j4 + 1]) * l4.y + wwi * Wpj[j4 + 1];
        ln.z = (1.f - wwi - Wwj[j4 + 2]) * l4.z + wwi * Wpj[j4 + 2];
        ln.w = (1.f - wwi - Wwj[j4 + 3]) * l4.w + wwi * Wpj[j4 + 3];
        if (it == jt) {
            if (il == j4 + 0) ln.x = 0.f;
            if (il == j4 + 1) ln.y = 0.f;
            if (il == j4 + 2) ln.z = 0.f;
            if (il == j4 + 3) ln.w = 0.f;
        }
        *(float4*)&Ln_s[il][j4] = ln;
        *(float4*)(Ln_out + gidx) = ln;
    }
    __syncthreads();
    {
        int il = t >> 2, r = t & 3;
        float accF = 0.f, accB = 0.f;
#pragma unroll
        for (int c = 0; c < 64; c++) {
            accF += Ln_s[il][c] * Wrj[c][r];   // fwd: row-reduction over j
            accB += Ln_s[c][il] * Wri[c][r];   // bwd: col-reduction over i
        }
        g_fwdpart[((b * 8 + jt) * NMEM + i0 + il) * RH + r] = accF;
        g_bwdpart[((b * 8 + it) * NMEM + j0 + il) * RH + r] = accB;
    }
}

// ---------------------------------------------------------------------------
// Fused: partial reduce + read content lookup + mode mix -> Wr_n
//        + read vectors + output projection. 64 blocks x 512 threads.
// ---------------------------------------------------------------------------
__global__ void read_fused_kernel(const float* __restrict__ Mn,
                                  const float* __restrict__ Wro,
                                  float* __restrict__ Wr_out,
                                  float* __restrict__ y_out) {
    __shared__ __align__(16) float fwd_s[NMEM * RH];   // 8KB
    __shared__ __align__(16) float bwd_s[NMEM * RH];   // 8KB
    __shared__ float Wrs[NMEM][RH];                    // 8KB
    __shared__ __align__(16) float nk[RH][WD];
    __shared__ float br[RH];
    __shared__ float m0s[RH], m1s[RH], m2s[RH];
    __shared__ float sb[16];
    __shared__ float part[512];
    __shared__ float rv[256];
    int b = blockIdx.x, t = threadIdx.x;
    const float* ifr = g_iface + (2 * b) * IFC;

    // reduce 8 partial tiles (float4)
    {
        float4 f4 = make_float4(0.f, 0.f, 0.f, 0.f);
        float4 b4 = make_float4(0.f, 0.f, 0.f, 0.f);
#pragma unroll
        for (int c = 0; c < 8; c++) {
            const float4* fp = (const float4*)(g_fwdpart + (b * 8 + c) * (NMEM * RH)) + t;
            const float4* bp = (const float4*)(g_bwdpart + (b * 8 + c) * (NMEM * RH)) + t;
            float4 fv = *fp, bv = *bp;
            f4.x += fv.x; f4.y += fv.y; f4.z += fv.z; f4.w += fv.w;
            b4.x += bv.x; b4.y += bv.y; b4.z += bv.z; b4.w += bv.w;
        }
        ((float4*)fwd_s)[t] = f4;
        ((float4*)bwd_s)[t] = b4;
    }
    if (t < RH * WD) {
        int r = t >> 6, w = t & 63;
        nk[r][w] = ifr[r * WD + w];
    }
    if (t >= 256 && t < 256 + RH) {
        int r = t - 256;
        br[r] = 1.f + softplusf_(ifr[256 + r]);
        float a = ifr[459 + r], bb = ifr[463 + r], c = ifr[467 + r];
        float mx = fmaxf(a, fmaxf(bb, c));
        float ea = expf(a - mx), eb = expf(bb - mx), ec = expf(c - mx);
        float s = ea + eb + ec;
        m0s[r] = ea / s; m1s[r] = eb / s; m2s[r] = ec / s;
    }
    __syncthreads();
    if (t < RH) {
        float s = 0.f;
        for (int w = 0; w < WD; w++) { float v = nk[t][w]; s += v * v; }
        float rn = 1.f / sqrtf(fmaxf(s, 1e-12f));
        for (int w = 0; w < WD; w++) nk[t][w] *= rn;
    }
    __syncthreads();

    // content lookup (4 heads, float4)
    const float4* m4p = (const float4*)(Mn + (b * NMEM + t) * WD);
    float d[RH] = {0.f, 0.f, 0.f, 0.f};
    float nrm = 0.f;
#pragma unroll
    for (int i = 0; i < 16; i++) {
        float4 m4 = m4p[i];
        nrm += m4.x * m4.x + m4.y * m4.y + m4.z * m4.z + m4.w * m4.w;
#pragma unroll
        for (int r = 0; r < RH; r++) {
            float4 k4 = ((const float4*)nk[r])[i];
            d[r] += m4.x * k4.x + m4.y * k4.y + m4.z * k4.z + m4.w * k4.w;
        }
    }
    float rn = 1.f / sqrtf(fmaxf(nrm, 1e-12f));
    float wl[RH];
#pragma unroll
    for (int r = 0; r < RH; r++) {
        float s = d[r] * rn * br[r];
        float mxv = blk_red_max(s, sb, t);
        float e = expf(s - mxv);
        float ssum = blk_red_sum(e, sb, t);
        wl[r] = e / ssum;
    }
#pragma unroll
    for (int r = 0; r < RH; r++) {
        float v = m0s[r] * bwd_s[t * RH + r] + m1s[r] * wl[r] + m2s[r] * fwd_s[t * RH + r];
        Wr_out[(b * NMEM + t) * RH + r] = v;
        Wrs[t][r] = v;
    }
    __syncthreads();

    // read vectors: rv[r*64+w] = sum_n Mn[n,w] * Wr[n,r]; all 512 threads
    {
        int half = t >> 8, tt = t & 255;
        int r = tt >> 6, w = tt & 63;
        int n0 = half * 256;
        float acc = 0.f;
#pragma unroll 8
        for (int n = 0; n < 256; n++)
            acc += Mn[(b * NMEM + n0 + n) * WD + w] * Wrs[n0 + n][r];
        part[t] = acc;
    }
    __syncthreads();
    if (t < 256) rv[t] = part[t] + part[256 + t];
    __syncthreads();
    // y = rv @ W_read_out ; all 512 threads (k-split)
    {
        int half = t >> 8, tt = t & 255;
        int k0 = half * 128;
        float ya = 0.f;
#pragma unroll 8
        for (int k = 0; k < 128; k++) ya += rv[k0 + k] * Wro[(k0 + k) * OUTD + tt];
        part[t] = ya;
    }
    __syncthreads();
    if (t < 256) y_out[b * OUTD + t] = part[t] + part[256 + t];
}

// ---------------------------------------------------------------------------
extern "C" void kernel_launch(void* const* d_in, const int* in_sizes, int n_in,
                              void* d_out, int out_size) {
    const float* inputs   = (const float*)d_in[0];
    const float* M        = (const float*)d_in[1];
    const float* usage    = (const float*)d_in[2];
    const float* L        = (const float*)d_in[3];
    const float* Wp       = (const float*)d_in[4];
    const float* W_read   = (const float*)d_in[5];
    const float* W_write  = (const float*)d_in[6];
    const float* h_ctrl   = (const float*)d_in[7];
    const float* W_iface  = (const float*)d_in[8];
    const float* W_rdout  = (const float*)d_in[9];
    const float* gru_k    = (const float*)d_in[10];
    const float* gru_rk   = (const float*)d_in[11];
    const float* gru_b    = (const float*)d_in[12];

    float* out = (float*)d_out;
    float* o_y    = out + OFF_Y;
    float* o_mn   = out + OFF_MN;
    float* o_use  = out + OFF_USAGE;
    float* o_ln   = out + OFF_LN;
    float* o_wp   = out + OFF_WP;
    float* o_wr   = out + OFF_WR;
    float* o_ww   = out + OFF_WW;
    float* o_hc   = out + OFF_HC;

    // 1) GRU mats mx & mh in one launch (32x32 tiles — measured fastest)
    gemm_gru<<<dim3((G3 + 31) / 32, 4, 2), 128>>>(inputs, h_ctrl, gru_k, gru_rk, gru_b);
    // 2) combine -> hc
    gru_combine<<<(128 * CD + 255) / 256, 256>>>(h_ctrl, o_hc);
    // 3) interface = hc @ W_interface
    gemm_iface<<<dim3((IFC + 31) / 32, 4), 128>>>(o_hc, W_iface);
    // 4) fused usage + alloc + write lookup + Ww + Wp (sort-free)
    memupdate_kernel<<<BSZ, NMEM>>>(W_read, W_write, usage, M, Wp,
                                    o_use, o_ww, o_wp);
    // 5) link update + fwd/bwd partials + M_n chunks (blocks 64..67)
    link_kernel<<<dim3(68, BSZ), 256>>>(L, o_ww, Wp, W_read, M, o_mn, o_ln);
    // 6) fused reduce + read lookup + Wr + read vectors + y
    read_fused_kernel<<<BSZ, NMEM>>>(o_mn, W_rdout, o_wr, o_y);
}